// round 12
// baseline (speedup 1.0000x reference)
#include <cuda_runtime.h>
#include <cuda_bf16.h>
#include <math.h>
#include <float.h>

#define Bq 4
#define Cc 192
#define Nn 1024
#define HD 384
#define NHEAD 4
#define KNB 16
#define HDTOT (NHEAD*HD)   // 1536
#define BNEPS 1e-5f
#define PAD 36             // smem row pitch (floats) for tf32 kernels
#define PAD2 20            // smem row pitch for K16 split kernels
#define DBUF (128*PAD2)    // one split buffer (floats)

// ---------------- scratch (no allocs allowed) ----------------
__device__ float g_y[Bq*Nn*Cc];                     // fc1 output [B,N,C]
__device__ float g_sq[Bq*Nn];                       // ||y||^2
__device__ float g_D[(size_t)Bq*Nn*Nn];             // pairwise distances
__device__ int   g_knn[Bq*Nn*KNB];                  // knn indices
__device__ __nv_bfloat16 g_h[(size_t)Bq*Nn*HDTOT];  // GAT lin output (bf16)
__device__ float g_as[Bq*Nn*NHEAD];                 // alpha_src
__device__ float g_ad[Bq*Nn*NHEAD];                 // alpha_dst
__device__ float g_ws[Cc*NHEAD];                    // Wg_h[:,c]·att_src_h
__device__ float g_wd[Cc*NHEAD];                    // Wg_h[:,c]·att_dst_h
__device__ float g_gg[(size_t)Bq*Nn*HD];            // post-GAT/BN/GELU [B,N,384]

// ================= tf32 mma building blocks =================
__device__ __forceinline__ unsigned to_tf32(float x) {
    unsigned r; asm("cvt.rna.tf32.f32 %0, %1;" : "=r"(r) : "f"(x)); return r;
}

__device__ __forceinline__ void mma8(float* d, const unsigned* a, const unsigned* b) {
    asm volatile("mma.sync.aligned.m16n8k8.row.col.f32.tf32.tf32.f32 "
        "{%0,%1,%2,%3}, {%4,%5,%6,%7}, {%8,%9}, {%0,%1,%2,%3};"
        : "+f"(d[0]), "+f"(d[1]), "+f"(d[2]), "+f"(d[3])
        : "r"(a[0]), "r"(a[1]), "r"(a[2]), "r"(a[3]), "r"(b[0]), "r"(b[1]));
}

__device__ __forceinline__ void mma_chunk(const float* As, const float* Bs,
                                          float acc[4][4][4], int wm, int wn,
                                          int g, int tig) {
#pragma unroll
    for (int ks = 0; ks < 4; ks++) {
        unsigned a[4][4], bf[4][2];
#pragma unroll
        for (int mt = 0; mt < 4; mt++) {
            const float* ap = As + (wm*64 + mt*16 + g)*PAD + ks*8 + tig;
            a[mt][0] = __float_as_uint(ap[0]);
            a[mt][2] = __float_as_uint(ap[4]);
            a[mt][1] = __float_as_uint(ap[8*PAD]);
            a[mt][3] = __float_as_uint(ap[8*PAD + 4]);
        }
#pragma unroll
        for (int nt = 0; nt < 4; nt++) {
            const float* bp = Bs + (wn*32 + nt*8 + g)*PAD + ks*8 + tig;
            bf[nt][0] = __float_as_uint(bp[0]);
            bf[nt][1] = __float_as_uint(bp[4]);
        }
#pragma unroll
        for (int mt = 0; mt < 4; mt++)
#pragma unroll
            for (int nt = 0; nt < 4; nt++)
                mma8(acc[mt][nt], a[mt], bf[nt]);
    }
}

template<int ROWS, int NT>
__device__ __forceinline__ void load_kmajor(float* S, const float* G, int ld, int tid) {
    for (int idx = tid; idx < ROWS*8; idx += NT) {
        int r = idx >> 3, k4 = (idx & 7) << 2;
        float4 v = *(const float4*)(G + r*ld + k4);
        float4 o;
        o.x = __uint_as_float(to_tf32(v.x)); o.y = __uint_as_float(to_tf32(v.y));
        o.z = __uint_as_float(to_tf32(v.z)); o.w = __uint_as_float(to_tf32(v.w));
        *(float4*)(S + r*PAD + k4) = o;
    }
}

template<int NT>
__device__ __forceinline__ void load_trans(float* S, const float* G, int ld, int tid) {
    for (int idx = tid; idx < 1024; idx += NT) {
        int kk = idx >> 5, m4 = (idx & 31) << 2;
        float4 v = *(const float4*)(G + kk*ld + m4);
        S[(m4+0)*PAD + kk] = __uint_as_float(to_tf32(v.x));
        S[(m4+1)*PAD + kk] = __uint_as_float(to_tf32(v.y));
        S[(m4+2)*PAD + kk] = __uint_as_float(to_tf32(v.z));
        S[(m4+3)*PAD + kk] = __uint_as_float(to_tf32(v.w));
    }
}

// split-load: ROWS x 16 K-chunk -> hi/lo tf32 pair (3xTF32 scheme)
template<int ROWS, int NT>
__device__ __forceinline__ void load_split(float* Shi, float* Slo,
                                           const float* G, int ld, int tid) {
    for (int idx = tid; idx < ROWS*4; idx += NT) {
        int r = idx >> 2, k4 = (idx & 3) << 2;
        float4 v = *(const float4*)(G + r*ld + k4);
        float4 hi, lo;
        hi.x = __uint_as_float(to_tf32(v.x)); lo.x = __uint_as_float(to_tf32(v.x - hi.x));
        hi.y = __uint_as_float(to_tf32(v.y)); lo.y = __uint_as_float(to_tf32(v.y - hi.y));
        hi.z = __uint_as_float(to_tf32(v.z)); lo.z = __uint_as_float(to_tf32(v.z - hi.z));
        hi.w = __uint_as_float(to_tf32(v.w)); lo.w = __uint_as_float(to_tf32(v.w - hi.w));
        *(float4*)(Shi + r*PAD2 + k4) = hi;
        *(float4*)(Slo + r*PAD2 + k4) = lo;
    }
}

// 3xTF32 K=16 chunk, warp tile 32(M)x32(N): acc += Alo*Bhi + Ahi*Blo + Ahi*Bhi
__device__ __forceinline__ void mma_chunk3_w32(const float* Ahi, const float* Alo,
                                               const float* Bhi, const float* Blo,
                                               float acc[2][4][4], int wm, int wn,
                                               int g, int tig) {
#pragma unroll
    for (int ks = 0; ks < 2; ks++) {
        unsigned ah[2][4], al[2][4], bh[4][2], bl[4][2];
#pragma unroll
        for (int mt = 0; mt < 2; mt++) {
            int off = (wm*32 + mt*16 + g)*PAD2 + ks*8 + tig;
            ah[mt][0] = __float_as_uint(Ahi[off]);
            ah[mt][2] = __float_as_uint(Ahi[off + 4]);
            ah[mt][1] = __float_as_uint(Ahi[off + 8*PAD2]);
            ah[mt][3] = __float_as_uint(Ahi[off + 8*PAD2 + 4]);
            al[mt][0] = __float_as_uint(Alo[off]);
            al[mt][2] = __float_as_uint(Alo[off + 4]);
            al[mt][1] = __float_as_uint(Alo[off + 8*PAD2]);
            al[mt][3] = __float_as_uint(Alo[off + 8*PAD2 + 4]);
        }
#pragma unroll
        for (int nt = 0; nt < 4; nt++) {
            int off = (wn*32 + nt*8 + g)*PAD2 + ks*8 + tig;
            bh[nt][0] = __float_as_uint(Bhi[off]);
            bh[nt][1] = __float_as_uint(Bhi[off + 4]);
            bl[nt][0] = __float_as_uint(Blo[off]);
            bl[nt][1] = __float_as_uint(Blo[off + 4]);
        }
#pragma unroll
        for (int mt = 0; mt < 2; mt++)
#pragma unroll
            for (int nt = 0; nt < 4; nt++) {
                mma8(acc[mt][nt], al[mt], bh[nt]);
                mma8(acc[mt][nt], ah[mt], bl[nt]);
                mma8(acc[mt][nt], ah[mt], bh[nt]);
            }
    }
}

__device__ __forceinline__ float wredsum(float v) {
#pragma unroll
    for (int off = 16; off; off >>= 1) v += __shfl_xor_sync(0xffffffffu, v, off);
    return v;
}

// ================= prep: ws/wd per (c,h) =================
__global__ void wsd_kernel(const float* __restrict__ Wg,
                           const float* __restrict__ att_src,
                           const float* __restrict__ att_dst) {
    int p = blockIdx.x * 8 + (threadIdx.x >> 5);   // 0..767
    int lane = threadIdx.x & 31;
    int c = p >> 2, h = p & 3;
    const float* wrow = Wg + (size_t)c*HDTOT + h*HD;
    const float* sv = att_src + h*HD;
    const float* dv = att_dst + h*HD;
    float s = 0.f, d = 0.f;
    for (int i = lane; i < HD; i += 32) { float w = wrow[i]; s += w*sv[i]; d += w*dv[i]; }
    s = wredsum(s); d = wredsum(d);
    if (!lane) { g_ws[c*4+h] = s; g_wd[c*4+h] = d; }
}

// ================= fc1 (fp32, exact selection path) =================
__global__ __launch_bounds__(256) void fc1_kernel(
    const float* __restrict__ x, const float* __restrict__ W1,
    const float* __restrict__ b1, const float* __restrict__ bn1) {
    const int b  = blockIdx.z;
    const int n0 = blockIdx.y * 64;
    const int c0 = blockIdx.x * 64;
    __shared__ float As[16][64];
    __shared__ float Bs[16][65];
    const int tid = threadIdx.x;
    const int tx = tid & 15, ty = tid >> 4;
    float acc[4][4] = {};
    const float* Xb = x + (size_t)b * Cc * Nn;
    for (int k0 = 0; k0 < Cc; k0 += 16) {
        {
            int kk = tid >> 4, mm = (tid & 15) << 2;
            *(float4*)&As[kk][mm] = *(const float4*)(Xb + (k0 + kk) * Nn + n0 + mm);
        }
        {
            int cc = tid >> 2, kk = (tid & 3) << 2;
            float4 v = *(const float4*)(W1 + (c0 + cc) * Cc + k0 + kk);
            Bs[kk+0][cc] = v.x; Bs[kk+1][cc] = v.y; Bs[kk+2][cc] = v.z; Bs[kk+3][cc] = v.w;
        }
        __syncthreads();
#pragma unroll
        for (int kk = 0; kk < 16; kk++) {
            float a[4], bb[4];
#pragma unroll
            for (int i = 0; i < 4; i++) a[i] = As[kk][ty*4+i];
#pragma unroll
            for (int j = 0; j < 4; j++) bb[j] = Bs[kk][tx*4+j];
#pragma unroll
            for (int i = 0; i < 4; i++)
#pragma unroll
                for (int j = 0; j < 4; j++) acc[i][j] += a[i]*bb[j];
        }
        __syncthreads();
    }
    float scl[4], sh[4];
#pragma unroll
    for (int j = 0; j < 4; j++) {
        int c = c0 + tx*4 + j;
        float s = bn1[c] * rsqrtf(bn1[576+c] + BNEPS);
        scl[j] = s;
        sh[j]  = bn1[192+c] + (b1[c] - bn1[384+c]) * s;
    }
#pragma unroll
    for (int i = 0; i < 4; i++) {
        int m = n0 + ty*4 + i;
        float4 o;
        o.x = acc[i][0]*scl[0] + sh[0];
        o.y = acc[i][1]*scl[1] + sh[1];
        o.z = acc[i][2]*scl[2] + sh[2];
        o.w = acc[i][3]*scl[3] + sh[3];
        *(float4*)&g_y[((size_t)b*Nn + m)*Cc + c0 + tx*4] = o;
    }
}

// ================= node stats: ||y||^2, a_src, a_dst (warp per node) =================
__global__ __launch_bounds__(256) void node_stats_kernel() {
    __shared__ float sws[Cc*NHEAD], swd[Cc*NHEAD];
    const int tid = threadIdx.x;
    for (int i = tid; i < Cc*NHEAD; i += 256) { sws[i] = g_ws[i]; swd[i] = g_wd[i]; }
    __syncthreads();
    const int node = blockIdx.x * 8 + (tid >> 5);
    const int lane = tid & 31;
    const float* yr = g_y + (size_t)node * Cc;
    float s2 = 0.f, ss[4] = {}, dd[4] = {};
    for (int i = lane; i < Cc; i += 32) {
        float yv = yr[i];
        s2 += yv*yv;
#pragma unroll
        for (int h = 0; h < 4; h++) {
            ss[h] += yv * sws[i*4+h];
            dd[h] += yv * swd[i*4+h];
        }
    }
    s2 = wredsum(s2);
#pragma unroll
    for (int h = 0; h < 4; h++) { ss[h] = wredsum(ss[h]); dd[h] = wredsum(dd[h]); }
    if (!lane) {
        g_sq[node] = s2;
#pragma unroll
        for (int h = 0; h < 4; h++) { g_as[node*4+h] = ss[h]; g_ad[node*4+h] = dd[h]; }
    }
}

// ================= dist: 3xTF32, symmetric, 512thr, double-buffered =================
__global__ __launch_bounds__(512) void dist_kernel() {
    extern __shared__ float smem[];   // 2 bufs x {Ahi,Alo,Bhi,Blo} x DBUF = 81920 B
    const int b = blockIdx.z;
    int t = blockIdx.x;
    int bi = 0, rem = t;
    while (rem >= 8 - bi) { rem -= 8 - bi; bi++; }
    const int bj = bi + rem;
    const int r0 = bi*128, c0 = bj*128;

    const int tid = threadIdx.x, lane = tid & 31, wid = tid >> 5;
    const int wm = wid & 3, wn = wid >> 2, g = lane >> 2, tig = lane & 3;
    float acc[2][4][4] = {};
    const float* Yb = g_y + (size_t)b * Nn * Cc;

    load_split<128,512>(smem,          smem + DBUF,   Yb + (size_t)r0*Cc, Cc, tid);
    load_split<128,512>(smem + 2*DBUF, smem + 3*DBUF, Yb + (size_t)c0*Cc, Cc, tid);
    __syncthreads();

    for (int c = 0; c < 12; c++) {
        float* cur = smem + (c & 1) * 4*DBUF;
        if (c + 1 < 12) {
            float* nxt = smem + ((c + 1) & 1) * 4*DBUF;
            int k0 = (c + 1) * 16;
            load_split<128,512>(nxt,          nxt + DBUF,   Yb + (size_t)r0*Cc + k0, Cc, tid);
            load_split<128,512>(nxt + 2*DBUF, nxt + 3*DBUF, Yb + (size_t)c0*Cc + k0, Cc, tid);
        }
        mma_chunk3_w32(cur, cur + DBUF, cur + 2*DBUF, cur + 3*DBUF, acc, wm, wn, g, tig);
        __syncthreads();
    }

    const float* sqb = g_sq + b * Nn;
    float* Db = g_D + (size_t)b * Nn * Nn;
    const bool mirror = (bi != bj);
#pragma unroll
    for (int nt = 0; nt < 4; nt++) {
        int n = c0 + wn*32 + nt*8 + tig*2;
        float q0 = sqb[n], q1 = sqb[n+1];
#pragma unroll
        for (int mt = 0; mt < 2; mt++) {
            int m = r0 + wm*32 + mt*16 + g;
            float sn0 = sqb[m], sn1 = sqb[m+8];
            float d00 = sn0 + q0 - 2.f*acc[mt][nt][0];
            float d01 = sn0 + q1 - 2.f*acc[mt][nt][1];
            float d10 = sn1 + q0 - 2.f*acc[mt][nt][2];
            float d11 = sn1 + q1 - 2.f*acc[mt][nt][3];
            float* p = &Db[(size_t)m*Nn + n];
            float2 v0 = { d00, d01 };
            float2 v1 = { d10, d11 };
            *(float2*)p = v0;
            *(float2*)(p + 8*Nn) = v1;
            if (mirror) {
                Db[(size_t)n*Nn + m]         = d00;
                Db[(size_t)(n+1)*Nn + m]     = d01;
                Db[(size_t)n*Nn + m + 8]     = d10;
                Db[(size_t)(n+1)*Nn + m + 8] = d11;
            }
        }
    }
}

// ================= top-k: warp-per-row, 32-bit packed reduction =================
__global__ void topk_kernel() {
    const int row  = blockIdx.x * 8 + (threadIdx.x >> 5);
    const int lane = threadIdx.x & 31;
    const float* Dr = g_D + (size_t)row * Nn;
    unsigned v[32];
#pragma unroll
    for (int j = 0; j < 32; j++) {
        unsigned u = __float_as_uint(Dr[j*32 + lane]);
        v[j] = (u & 0x80000000u) ? ~u : (u | 0x80000000u);
    }
    unsigned bestv = v[0]; int bestj = 0;
#pragma unroll
    for (int j = 1; j < 32; j++) if (v[j] < bestv) { bestv = v[j]; bestj = j; }
    for (int s = 0; s < KNB; s++) {
        unsigned key = (bestv & 0xFFFFFFE0u) | (unsigned)lane;
#pragma unroll
        for (int off = 16; off; off >>= 1) {
            unsigned o = __shfl_xor_sync(0xffffffffu, key, off);
            if (o < key) key = o;
        }
        int L = key & 31;
        int bj = __shfl_sync(0xffffffffu, bestj, L);
        int gidx = bj*32 + L;
        if (lane == 0) g_knn[row*KNB + s] = gidx;
        if (lane == L) {
#pragma unroll
            for (int j = 0; j < 32; j++) if (j == bj) v[j] = 0xFFFFFFFFu;
            bestv = v[0]; bestj = 0;
#pragma unroll
            for (int j = 1; j < 32; j++) if (v[j] < bestv) { bestv = v[j]; bestj = j; }
        }
    }
}

// ================= h = y @ Wg (tf32, CTA 128x128, bf16 output) =================
__global__ __launch_bounds__(256) void hgemm_kernel(const float* __restrict__ Wg) {
    const int b = blockIdx.z, m0 = blockIdx.y*128, j0 = blockIdx.x*128;
    __shared__ float As[128*PAD], Bs[128*PAD];
    const int tid = threadIdx.x, lane = tid & 31, wid = tid >> 5;
    const int wm = wid & 1, wn = wid >> 1, g = lane >> 2, tig = lane & 3;
    float acc[4][4][4] = {};
    const float* Yb = g_y + (size_t)b * Nn * Cc;
    for (int k0 = 0; k0 < Cc; k0 += 32) {
        load_kmajor<128,256>(As, Yb + (size_t)m0*Cc + k0, Cc, tid);
        load_trans<256>(Bs, Wg + (size_t)k0*HDTOT + j0, HDTOT, tid);
        __syncthreads();
        mma_chunk(As, Bs, acc, wm, wn, g, tig);
        __syncthreads();
    }
#pragma unroll
    for (int nt = 0; nt < 4; nt++) {
        int j = j0 + wn*32 + nt*8 + tig*2;
#pragma unroll
        for (int mt = 0; mt < 4; mt++) {
            int m = m0 + wm*64 + mt*16 + g;
            __nv_bfloat16* p = &g_h[((size_t)b*Nn + m)*HDTOT + j];
            *(__nv_bfloat162*)p =
                __float22bfloat162_rn(make_float2(acc[mt][nt][0], acc[mt][nt][1]));
            *(__nv_bfloat162*)(p + 8*HDTOT) =
                __float22bfloat162_rn(make_float2(acc[mt][nt][2], acc[mt][nt][3]));
        }
    }
}

// ================= GAT aggregate: cp.async smem-staged gather + BN + GELU =================
__global__ __launch_bounds__(192) void gat_kernel(
    const float* __restrict__ bg, const float* __restrict__ bng) {
    extern __shared__ __nv_bfloat16 sh[];   // [KNB][HDTOT] = 49152 B
    __shared__ int   nbr[KNB];
    __shared__ float attw[KNB][NHEAD];
    const int node = blockIdx.x;       // b*1024+n
    const int b = node >> 10;
    const int tid = threadIdx.x;       // 192
    if (tid < KNB) nbr[tid] = g_knn[node*KNB + tid];
    __syncthreads();

    // stage all 16 neighbor rows: thread t copies float4 #t of each row (coalesced)
    unsigned s_base = (unsigned)__cvta_generic_to_shared(sh);
#pragma unroll
    for (int k = 0; k < KNB; k++) {
        const char* src = (const char*)&g_h[(size_t)(b*Nn + nbr[k]) * HDTOT] + tid*16;
        unsigned dst = s_base + k*(HDTOT*2) + tid*16;
        asm volatile("cp.async.cg.shared.global [%0], [%1], 16;\n"
                     :: "r"(dst), "l"(src) : "memory");
    }
    asm volatile("cp.async.commit_group;\n" ::: "memory");

    // overlap: attention logits + softmax while the copies land
    if (tid < KNB*NHEAD) {
        int k = tid >> 2, h = tid & 3;
        float e = g_as[(b*Nn + nbr[k])*NHEAD + h] + g_ad[node*NHEAD + h];
        attw[k][h] = e > 0.f ? e : 0.2f*e;
    }
    __syncthreads();
    if (tid < NHEAD) {
        float mx = -FLT_MAX;
        for (int k = 0; k < KNB; k++) mx = fmaxf(mx, attw[k][tid]);
        float s = 0.f;
        for (int k = 0; k < KNB; k++) { float t = expf(attw[k][tid]-mx); attw[k][tid] = t; s += t; }
        float inv = 1.f/s;
        for (int k = 0; k < KNB; k++) attw[k][tid] *= inv;
    }
    asm volatile("cp.async.wait_group 0;\n" ::: "memory");
    __syncthreads();

    // aggregate from smem: thread owns dims (2*tid, 2*tid+1); conflict-free LDS
    const __nv_bfloat162* sh2 = (const __nv_bfloat162*)sh;
    float ax = 0.f, ay = 0.f;
    for (int k = 0; k < KNB; k++) {
        const __nv_bfloat162* row = sh2 + k*(HDTOT/2);
#pragma unroll
        for (int h = 0; h < NHEAD; h++) {
            float w = attw[k][h];
            float2 f = __bfloat1622float2(row[h*(HD/2) + tid]);
            ax += w * f.x;
            ay += w * f.y;
        }
    }
    int d = tid * 2;
#pragma unroll
    for (int e = 0; e < 2; e++) {
        float a = (e == 0) ? ax : ay;
        int dd = d + e;
        float v = a*0.25f + bg[dd];
        v = (v - bng[2*HD + dd]) * (bng[dd] * rsqrtf(bng[3*HD + dd] + BNEPS)) + bng[HD + dd];
        v = 0.5f * v * (1.f + erff(v * 0.70710678118654752440f));   // exact GELU
        g_gg[(size_t)node*HD + dd] = v;
    }
}

// ================= fc2 (tf32, CTA 128x96, 192thr) =================
__global__ __launch_bounds__(192) void fc2_kernel(
    const float* __restrict__ W2, const float* __restrict__ b2,
    const float* __restrict__ bn2, const float* __restrict__ x,
    float* __restrict__ out) {
    const int b = blockIdx.z, m0 = blockIdx.y*128, c0 = blockIdx.x*96;
    __shared__ float As[128*PAD], Bs[96*PAD];
    const int tid = threadIdx.x, lane = tid & 31, wid = tid >> 5;
    const int wm = wid & 1, wn = wid >> 1, g = lane >> 2, tig = lane & 3;
    float acc[4][4][4] = {};
    const float* Gb = g_gg + (size_t)b * Nn * HD;
    for (int k0 = 0; k0 < HD; k0 += 32) {
        load_kmajor<128,192>(As, Gb + (size_t)m0*HD + k0, HD, tid);
        load_kmajor<96,192>(Bs, W2 + (size_t)c0*HD + k0, HD, tid);
        __syncthreads();
        mma_chunk(As, Bs, acc, wm, wn, g, tig);
        __syncthreads();
    }
#pragma unroll
    for (int nt = 0; nt < 4; nt++) {
        int c = c0 + wn*32 + nt*8 + tig*2;
        float s0 = bn2[c]   * rsqrtf(bn2[576+c]   + BNEPS);
        float s1 = bn2[c+1] * rsqrtf(bn2[576+c+1] + BNEPS);
        float h0 = bn2[192+c]   + (b2[c]   - bn2[384+c])   * s0;
        float h1 = bn2[192+c+1] + (b2[c+1] - bn2[384+c+1]) * s1;
#pragma unroll
        for (int mt = 0; mt < 4; mt++) {
            int m = m0 + wm*64 + mt*16 + g;
            size_t i00 = ((size_t)b*Cc + c)*Nn + m;    // out[c][m]
            out[i00]          = acc[mt][nt][0]*s0 + h0 + x[i00];
            out[i00 + Nn]     = acc[mt][nt][1]*s1 + h1 + x[i00 + Nn];
            out[i00 + 8]      = acc[mt][nt][2]*s0 + h0 + x[i00 + 8];
            out[i00 + Nn + 8] = acc[mt][nt][3]*s1 + h1 + x[i00 + Nn + 8];
        }
    }
}

// ================= launch (single stream) =================
extern "C" void kernel_launch(void* const* d_in, const int* in_sizes, int n_in,
                              void* d_out, int out_size) {
    const float* x       = (const float*)d_in[0];
    const float* W1      = (const float*)d_in[1];
    const float* b1      = (const float*)d_in[2];
    const float* bn1     = (const float*)d_in[3];
    const float* Wg      = (const float*)d_in[4];
    const float* att_src = (const float*)d_in[5];
    const float* att_dst = (const float*)d_in[6];
    const float* bg      = (const float*)d_in[7];
    const float* bng     = (const float*)d_in[8];
    const float* W2      = (const float*)d_in[9];
    const float* b2      = (const float*)d_in[10];
    const float* bn2     = (const float*)d_in[11];
    float* out = (float*)d_out;

    const int dist_smem = 2 * 4 * DBUF * (int)sizeof(float);   // 81920 B
    cudaFuncSetAttribute(dist_kernel,
                         cudaFuncAttributeMaxDynamicSharedMemorySize, dist_smem);
    const int gat_smem = KNB * HDTOT * (int)sizeof(__nv_bfloat16);  // 49152 B
    cudaFuncSetAttribute(gat_kernel,
                         cudaFuncAttributeMaxDynamicSharedMemorySize, gat_smem);

    wsd_kernel<<<96, 256>>>(Wg, att_src, att_dst);            // 1
    fc1_kernel<<<dim3(3, 16, Bq), 256>>>(x, W1, b1, bn1);     // 2
    node_stats_kernel<<<512, 256>>>();                        // 3
    dist_kernel<<<dim3(36, 1, Bq), 512, dist_smem>>>();       // 4 (profiled)
    topk_kernel<<<512, 256>>>();                              // 5
    hgemm_kernel<<<dim3(12, 8, Bq), 256>>>(Wg);               // 6
    gat_kernel<<<Bq*Nn, 192, gat_smem>>>(bg, bng);            // 7
    fc2_kernel<<<dim3(2, 8, Bq), 192>>>(W2, b2, bn2, x, out); // 8
}

// round 13
// speedup vs baseline: 1.0825x; 1.0825x over previous
#include <cuda_runtime.h>
#include <cuda_bf16.h>
#include <math.h>
#include <float.h>

#define Bq 4
#define Cc 192
#define Nn 1024
#define HD 384
#define NHEAD 4
#define KNB 16
#define HDTOT (NHEAD*HD)   // 1536
#define BNEPS 1e-5f
#define PAD 36             // smem row pitch (floats) for tf32 kernels
#define PAD2 20            // smem row pitch for K16 split kernels
#define DBUF (128*PAD2)    // one split buffer (floats)

// ---------------- scratch (no allocs allowed) ----------------
__device__ float g_y[Bq*Nn*Cc];                     // fc1 output [B,N,C]
__device__ float g_sq[Bq*Nn];                       // ||y||^2
__device__ float g_D[(size_t)Bq*Nn*Nn];             // pairwise distances
__device__ int   g_knn[Bq*Nn*KNB];                  // knn indices
__device__ __nv_bfloat16 g_h[(size_t)Bq*Nn*HDTOT];  // GAT lin output (bf16)
__device__ float g_as[Bq*Nn*NHEAD];                 // alpha_src
__device__ float g_ad[Bq*Nn*NHEAD];                 // alpha_dst
__device__ float g_ws[Cc*NHEAD];                    // Wg_h[:,c]·att_src_h
__device__ float g_wd[Cc*NHEAD];                    // Wg_h[:,c]·att_dst_h
__device__ float g_gg[(size_t)Bq*Nn*HD];            // post-GAT/BN/GELU [B,N,384]

// ================= tf32 mma building blocks =================
__device__ __forceinline__ unsigned to_tf32(float x) {
    unsigned r; asm("cvt.rna.tf32.f32 %0, %1;" : "=r"(r) : "f"(x)); return r;
}

__device__ __forceinline__ void mma8(float* d, const unsigned* a, const unsigned* b) {
    asm volatile("mma.sync.aligned.m16n8k8.row.col.f32.tf32.tf32.f32 "
        "{%0,%1,%2,%3}, {%4,%5,%6,%7}, {%8,%9}, {%0,%1,%2,%3};"
        : "+f"(d[0]), "+f"(d[1]), "+f"(d[2]), "+f"(d[3])
        : "r"(a[0]), "r"(a[1]), "r"(a[2]), "r"(a[3]), "r"(b[0]), "r"(b[1]));
}

__device__ __forceinline__ void mma_chunk(const float* As, const float* Bs,
                                          float acc[4][4][4], int wm, int wn,
                                          int g, int tig) {
#pragma unroll
    for (int ks = 0; ks < 4; ks++) {
        unsigned a[4][4], bf[4][2];
#pragma unroll
        for (int mt = 0; mt < 4; mt++) {
            const float* ap = As + (wm*64 + mt*16 + g)*PAD + ks*8 + tig;
            a[mt][0] = __float_as_uint(ap[0]);
            a[mt][2] = __float_as_uint(ap[4]);
            a[mt][1] = __float_as_uint(ap[8*PAD]);
            a[mt][3] = __float_as_uint(ap[8*PAD + 4]);
        }
#pragma unroll
        for (int nt = 0; nt < 4; nt++) {
            const float* bp = Bs + (wn*32 + nt*8 + g)*PAD + ks*8 + tig;
            bf[nt][0] = __float_as_uint(bp[0]);
            bf[nt][1] = __float_as_uint(bp[4]);
        }
#pragma unroll
        for (int mt = 0; mt < 4; mt++)
#pragma unroll
            for (int nt = 0; nt < 4; nt++)
                mma8(acc[mt][nt], a[mt], bf[nt]);
    }
}

template<int ROWS, int NT>
__device__ __forceinline__ void load_kmajor(float* S, const float* G, int ld, int tid) {
    for (int idx = tid; idx < ROWS*8; idx += NT) {
        int r = idx >> 3, k4 = (idx & 7) << 2;
        float4 v = *(const float4*)(G + r*ld + k4);
        float4 o;
        o.x = __uint_as_float(to_tf32(v.x)); o.y = __uint_as_float(to_tf32(v.y));
        o.z = __uint_as_float(to_tf32(v.z)); o.w = __uint_as_float(to_tf32(v.w));
        *(float4*)(S + r*PAD + k4) = o;
    }
}

template<int NT>
__device__ __forceinline__ void load_trans(float* S, const float* G, int ld, int tid) {
    for (int idx = tid; idx < 1024; idx += NT) {
        int kk = idx >> 5, m4 = (idx & 31) << 2;
        float4 v = *(const float4*)(G + kk*ld + m4);
        S[(m4+0)*PAD + kk] = __uint_as_float(to_tf32(v.x));
        S[(m4+1)*PAD + kk] = __uint_as_float(to_tf32(v.y));
        S[(m4+2)*PAD + kk] = __uint_as_float(to_tf32(v.z));
        S[(m4+3)*PAD + kk] = __uint_as_float(to_tf32(v.w));
    }
}

// split-load: ROWS x 16 K-chunk -> hi/lo tf32 pair (3xTF32 scheme)
template<int ROWS, int NT>
__device__ __forceinline__ void load_split(float* Shi, float* Slo,
                                           const float* G, int ld, int tid) {
    for (int idx = tid; idx < ROWS*4; idx += NT) {
        int r = idx >> 2, k4 = (idx & 3) << 2;
        float4 v = *(const float4*)(G + r*ld + k4);
        float4 hi, lo;
        hi.x = __uint_as_float(to_tf32(v.x)); lo.x = __uint_as_float(to_tf32(v.x - hi.x));
        hi.y = __uint_as_float(to_tf32(v.y)); lo.y = __uint_as_float(to_tf32(v.y - hi.y));
        hi.z = __uint_as_float(to_tf32(v.z)); lo.z = __uint_as_float(to_tf32(v.z - hi.z));
        hi.w = __uint_as_float(to_tf32(v.w)); lo.w = __uint_as_float(to_tf32(v.w - hi.w));
        *(float4*)(Shi + r*PAD2 + k4) = hi;
        *(float4*)(Slo + r*PAD2 + k4) = lo;
    }
}

// 3xTF32 K=16 chunk, warp tile 32(M)x32(N): acc += Alo*Bhi + Ahi*Blo + Ahi*Bhi
__device__ __forceinline__ void mma_chunk3_w32(const float* Ahi, const float* Alo,
                                               const float* Bhi, const float* Blo,
                                               float acc[2][4][4], int wm, int wn,
                                               int g, int tig) {
#pragma unroll
    for (int ks = 0; ks < 2; ks++) {
        unsigned ah[2][4], al[2][4], bh[4][2], bl[4][2];
#pragma unroll
        for (int mt = 0; mt < 2; mt++) {
            int off = (wm*32 + mt*16 + g)*PAD2 + ks*8 + tig;
            ah[mt][0] = __float_as_uint(Ahi[off]);
            ah[mt][2] = __float_as_uint(Ahi[off + 4]);
            ah[mt][1] = __float_as_uint(Ahi[off + 8*PAD2]);
            ah[mt][3] = __float_as_uint(Ahi[off + 8*PAD2 + 4]);
            al[mt][0] = __float_as_uint(Alo[off]);
            al[mt][2] = __float_as_uint(Alo[off + 4]);
            al[mt][1] = __float_as_uint(Alo[off + 8*PAD2]);
            al[mt][3] = __float_as_uint(Alo[off + 8*PAD2 + 4]);
        }
#pragma unroll
        for (int nt = 0; nt < 4; nt++) {
            int off = (wn*32 + nt*8 + g)*PAD2 + ks*8 + tig;
            bh[nt][0] = __float_as_uint(Bhi[off]);
            bh[nt][1] = __float_as_uint(Bhi[off + 4]);
            bl[nt][0] = __float_as_uint(Blo[off]);
            bl[nt][1] = __float_as_uint(Blo[off + 4]);
        }
#pragma unroll
        for (int mt = 0; mt < 2; mt++)
#pragma unroll
            for (int nt = 0; nt < 4; nt++) {
                mma8(acc[mt][nt], al[mt], bh[nt]);
                mma8(acc[mt][nt], ah[mt], bl[nt]);
                mma8(acc[mt][nt], ah[mt], bh[nt]);
            }
    }
}

__device__ __forceinline__ float wredsum(float v) {
#pragma unroll
    for (int off = 16; off; off >>= 1) v += __shfl_xor_sync(0xffffffffu, v, off);
    return v;
}

// ================= device bodies (shared by fused kernels) =================

__device__ __forceinline__ void wsd_body(const float* __restrict__ Wg,
                                         const float* __restrict__ att_src,
                                         const float* __restrict__ att_dst,
                                         int bid) {
    int p = bid * 8 + ((int)threadIdx.x >> 5);   // 0..767
    int lane = threadIdx.x & 31;
    int c = p >> 2, h = p & 3;
    const float* wrow = Wg + (size_t)c*HDTOT + h*HD;
    const float* sv = att_src + h*HD;
    const float* dv = att_dst + h*HD;
    float s = 0.f, d = 0.f;
    for (int i = lane; i < HD; i += 32) { float w = wrow[i]; s += w*sv[i]; d += w*dv[i]; }
    s = wredsum(s); d = wredsum(d);
    if (!lane) { g_ws[c*4+h] = s; g_wd[c*4+h] = d; }
}

__device__ __forceinline__ void fc1_body(const float* __restrict__ x,
                                         const float* __restrict__ W1,
                                         const float* __restrict__ b1,
                                         const float* __restrict__ bn1,
                                         int b, int n0, int c0) {
    __shared__ float As[16][64];
    __shared__ float Bs[16][65];
    const int tid = threadIdx.x;
    const int tx = tid & 15, ty = tid >> 4;
    float acc[4][4] = {};
    const float* Xb = x + (size_t)b * Cc * Nn;
    for (int k0 = 0; k0 < Cc; k0 += 16) {
        {
            int kk = tid >> 4, mm = (tid & 15) << 2;
            *(float4*)&As[kk][mm] = *(const float4*)(Xb + (k0 + kk) * Nn + n0 + mm);
        }
        {
            int cc = tid >> 2, kk = (tid & 3) << 2;
            float4 v = *(const float4*)(W1 + (c0 + cc) * Cc + k0 + kk);
            Bs[kk+0][cc] = v.x; Bs[kk+1][cc] = v.y; Bs[kk+2][cc] = v.z; Bs[kk+3][cc] = v.w;
        }
        __syncthreads();
#pragma unroll
        for (int kk = 0; kk < 16; kk++) {
            float a[4], bb[4];
#pragma unroll
            for (int i = 0; i < 4; i++) a[i] = As[kk][ty*4+i];
#pragma unroll
            for (int j = 0; j < 4; j++) bb[j] = Bs[kk][tx*4+j];
#pragma unroll
            for (int i = 0; i < 4; i++)
#pragma unroll
                for (int j = 0; j < 4; j++) acc[i][j] += a[i]*bb[j];
        }
        __syncthreads();
    }
    float scl[4], sh[4];
#pragma unroll
    for (int j = 0; j < 4; j++) {
        int c = c0 + tx*4 + j;
        float s = bn1[c] * rsqrtf(bn1[576+c] + BNEPS);
        scl[j] = s;
        sh[j]  = bn1[192+c] + (b1[c] - bn1[384+c]) * s;
    }
#pragma unroll
    for (int i = 0; i < 4; i++) {
        int m = n0 + ty*4 + i;
        float4 o;
        o.x = acc[i][0]*scl[0] + sh[0];
        o.y = acc[i][1]*scl[1] + sh[1];
        o.z = acc[i][2]*scl[2] + sh[2];
        o.w = acc[i][3]*scl[3] + sh[3];
        *(float4*)&g_y[((size_t)b*Nn + m)*Cc + c0 + tx*4] = o;
    }
}

__device__ __forceinline__ void topk_body(int bid) {
    const int row  = bid * 8 + ((int)threadIdx.x >> 5);
    const int lane = threadIdx.x & 31;
    const float* Dr = g_D + (size_t)row * Nn;
    unsigned v[32];
#pragma unroll
    for (int j = 0; j < 32; j++) {
        unsigned u = __float_as_uint(Dr[j*32 + lane]);
        v[j] = (u & 0x80000000u) ? ~u : (u | 0x80000000u);
    }
    unsigned bestv = v[0]; int bestj = 0;
#pragma unroll
    for (int j = 1; j < 32; j++) if (v[j] < bestv) { bestv = v[j]; bestj = j; }
    for (int s = 0; s < KNB; s++) {
        unsigned key = (bestv & 0xFFFFFFE0u) | (unsigned)lane;
#pragma unroll
        for (int off = 16; off; off >>= 1) {
            unsigned o = __shfl_xor_sync(0xffffffffu, key, off);
            if (o < key) key = o;
        }
        int L = key & 31;
        int bj = __shfl_sync(0xffffffffu, bestj, L);
        int gidx = bj*32 + L;
        if (lane == 0) g_knn[row*KNB + s] = gidx;
        if (lane == L) {
#pragma unroll
            for (int j = 0; j < 32; j++) if (j == bj) v[j] = 0xFFFFFFFFu;
            bestv = v[0]; bestj = 0;
#pragma unroll
            for (int j = 1; j < 32; j++) if (v[j] < bestv) { bestv = v[j]; bestj = j; }
        }
    }
}

__device__ __forceinline__ void hgemm_body(const float* __restrict__ Wg,
                                           int b, int m0, int j0) {
    __shared__ float As[128*PAD], Bs[128*PAD];
    const int tid = threadIdx.x, lane = tid & 31, wid = tid >> 5;
    const int wm = wid & 1, wn = wid >> 1, g = lane >> 2, tig = lane & 3;
    float acc[4][4][4] = {};
    const float* Yb = g_y + (size_t)b * Nn * Cc;
    for (int k0 = 0; k0 < Cc; k0 += 32) {
        load_kmajor<128,256>(As, Yb + (size_t)m0*Cc + k0, Cc, tid);
        load_trans<256>(Bs, Wg + (size_t)k0*HDTOT + j0, HDTOT, tid);
        __syncthreads();
        mma_chunk(As, Bs, acc, wm, wn, g, tig);
        __syncthreads();
    }
#pragma unroll
    for (int nt = 0; nt < 4; nt++) {
        int j = j0 + wn*32 + nt*8 + tig*2;
#pragma unroll
        for (int mt = 0; mt < 4; mt++) {
            int m = m0 + wm*64 + mt*16 + g;
            __nv_bfloat16* p = &g_h[((size_t)b*Nn + m)*HDTOT + j];
            *(__nv_bfloat162*)p =
                __float22bfloat162_rn(make_float2(acc[mt][nt][0], acc[mt][nt][1]));
            *(__nv_bfloat162*)(p + 8*HDTOT) =
                __float22bfloat162_rn(make_float2(acc[mt][nt][2], acc[mt][nt][3]));
        }
    }
}

// ================= fused launch 1: wsd (96 blocks) + fc1 (192 blocks) =================
__global__ __launch_bounds__(256) void pre_kernel(
    const float* __restrict__ x, const float* __restrict__ W1,
    const float* __restrict__ b1, const float* __restrict__ bn1,
    const float* __restrict__ Wg, const float* __restrict__ att_src,
    const float* __restrict__ att_dst) {
    int bid = blockIdx.x;
    if (bid < 96) {
        wsd_body(Wg, att_src, att_dst, bid);
    } else {
        int idx = bid - 96;                 // 0..191
        int b   = idx / 48;
        int rem = idx % 48;
        int c0  = (rem % 3) * 64;
        int n0  = (rem / 3) * 64;
        fc1_body(x, W1, b1, bn1, b, n0, c0);
    }
}

// ================= node stats: ||y||^2, a_src, a_dst (warp per node) =================
__global__ __launch_bounds__(256) void node_stats_kernel() {
    __shared__ float sws[Cc*NHEAD], swd[Cc*NHEAD];
    const int tid = threadIdx.x;
    for (int i = tid; i < Cc*NHEAD; i += 256) { sws[i] = g_ws[i]; swd[i] = g_wd[i]; }
    __syncthreads();
    const int node = blockIdx.x * 8 + (tid >> 5);
    const int lane = tid & 31;
    const float* yr = g_y + (size_t)node * Cc;
    float s2 = 0.f, ss[4] = {}, dd[4] = {};
    for (int i = lane; i < Cc; i += 32) {
        float yv = yr[i];
        s2 += yv*yv;
#pragma unroll
        for (int h = 0; h < 4; h++) {
            ss[h] += yv * sws[i*4+h];
            dd[h] += yv * swd[i*4+h];
        }
    }
    s2 = wredsum(s2);
#pragma unroll
    for (int h = 0; h < 4; h++) { ss[h] = wredsum(ss[h]); dd[h] = wredsum(dd[h]); }
    if (!lane) {
        g_sq[node] = s2;
#pragma unroll
        for (int h = 0; h < 4; h++) { g_as[node*4+h] = ss[h]; g_ad[node*4+h] = dd[h]; }
    }
}

// ================= dist: 3xTF32, symmetric, 512thr, double-buffered =================
__global__ __launch_bounds__(512) void dist_kernel() {
    extern __shared__ float smem[];   // 2 bufs x {Ahi,Alo,Bhi,Blo} x DBUF = 81920 B
    const int b = blockIdx.z;
    int t = blockIdx.x;
    int bi = 0, rem = t;
    while (rem >= 8 - bi) { rem -= 8 - bi; bi++; }
    const int bj = bi + rem;
    const int r0 = bi*128, c0 = bj*128;

    const int tid = threadIdx.x, lane = tid & 31, wid = tid >> 5;
    const int wm = wid & 3, wn = wid >> 2, g = lane >> 2, tig = lane & 3;
    float acc[2][4][4] = {};
    const float* Yb = g_y + (size_t)b * Nn * Cc;

    load_split<128,512>(smem,          smem + DBUF,   Yb + (size_t)r0*Cc, Cc, tid);
    load_split<128,512>(smem + 2*DBUF, smem + 3*DBUF, Yb + (size_t)c0*Cc, Cc, tid);
    __syncthreads();

    for (int c = 0; c < 12; c++) {
        float* cur = smem + (c & 1) * 4*DBUF;
        if (c + 1 < 12) {
            float* nxt = smem + ((c + 1) & 1) * 4*DBUF;
            int k0 = (c + 1) * 16;
            load_split<128,512>(nxt,          nxt + DBUF,   Yb + (size_t)r0*Cc + k0, Cc, tid);
            load_split<128,512>(nxt + 2*DBUF, nxt + 3*DBUF, Yb + (size_t)c0*Cc + k0, Cc, tid);
        }
        mma_chunk3_w32(cur, cur + DBUF, cur + 2*DBUF, cur + 3*DBUF, acc, wm, wn, g, tig);
        __syncthreads();
    }

    const float* sqb = g_sq + b * Nn;
    float* Db = g_D + (size_t)b * Nn * Nn;
    const bool mirror = (bi != bj);
#pragma unroll
    for (int nt = 0; nt < 4; nt++) {
        int n = c0 + wn*32 + nt*8 + tig*2;
        float q0 = sqb[n], q1 = sqb[n+1];
#pragma unroll
        for (int mt = 0; mt < 2; mt++) {
            int m = r0 + wm*32 + mt*16 + g;
            float sn0 = sqb[m], sn1 = sqb[m+8];
            float d00 = sn0 + q0 - 2.f*acc[mt][nt][0];
            float d01 = sn0 + q1 - 2.f*acc[mt][nt][1];
            float d10 = sn1 + q0 - 2.f*acc[mt][nt][2];
            float d11 = sn1 + q1 - 2.f*acc[mt][nt][3];
            float* p = &Db[(size_t)m*Nn + n];
            float2 v0 = { d00, d01 };
            float2 v1 = { d10, d11 };
            *(float2*)p = v0;
            *(float2*)(p + 8*Nn) = v1;
            if (mirror) {
                Db[(size_t)n*Nn + m]         = d00;
                Db[(size_t)(n+1)*Nn + m]     = d01;
                Db[(size_t)n*Nn + m + 8]     = d10;
                Db[(size_t)(n+1)*Nn + m + 8] = d11;
            }
        }
    }
}

// ================= fused launch 2: topk (512 blocks) + hgemm (384 blocks) =================
__global__ __launch_bounds__(256) void mid_kernel(const float* __restrict__ Wg) {
    int bid = blockIdx.x;
    if (bid < 512) {
        topk_body(bid);
    } else {
        int idx = bid - 512;                // 0..383
        int b   = idx / 96;
        int rem = idx % 96;
        int j0  = (rem % 12) * 128;
        int m0  = (rem / 12) * 128;
        hgemm_body(Wg, b, m0, j0);
    }
}

// ================= GAT aggregate (bf16 h, direct gather) + BN + GELU =================
__global__ __launch_bounds__(192) void gat_kernel(
    const float* __restrict__ bg, const float* __restrict__ bng) {
    const int node = blockIdx.x;       // b*1024+n
    const int b = node >> 10;
    __shared__ int   nbr[KNB];
    __shared__ float attw[KNB][NHEAD];
    const int tid = threadIdx.x;       // 192
    if (tid < KNB) nbr[tid] = g_knn[node*KNB + tid];
    __syncthreads();
    if (tid < KNB*NHEAD) {
        int k = tid >> 2, h = tid & 3;
        float e = g_as[(b*Nn + nbr[k])*NHEAD + h] + g_ad[node*NHEAD + h];
        attw[k][h] = e > 0.f ? e : 0.2f*e;
    }
    __syncthreads();
    if (tid < NHEAD) {
        float mx = -FLT_MAX;
        for (int k = 0; k < KNB; k++) mx = fmaxf(mx, attw[k][tid]);
        float s = 0.f;
        for (int k = 0; k < KNB; k++) { float t = expf(attw[k][tid]-mx); attw[k][tid] = t; s += t; }
        float inv = 1.f/s;
        for (int k = 0; k < KNB; k++) attw[k][tid] *= inv;
    }
    __syncthreads();
    float ax = 0.f, ay = 0.f;
    for (int k = 0; k < KNB; k++) {
        const __nv_bfloat162* hb =
            (const __nv_bfloat162*)&g_h[(size_t)(b*Nn + nbr[k]) * HDTOT];
#pragma unroll
        for (int h = 0; h < NHEAD; h++) {
            float w = attw[k][h];
            float2 f = __bfloat1622float2(hb[h*(HD/2) + tid]);
            ax += w * f.x;
            ay += w * f.y;
        }
    }
    int d = tid * 2;
#pragma unroll
    for (int e = 0; e < 2; e++) {
        float a = (e == 0) ? ax : ay;
        int dd = d + e;
        float v = a*0.25f + bg[dd];
        v = (v - bng[2*HD + dd]) * (bng[dd] * rsqrtf(bng[3*HD + dd] + BNEPS)) + bng[HD + dd];
        v = 0.5f * v * (1.f + erff(v * 0.70710678118654752440f));   // exact GELU
        g_gg[(size_t)node*HD + dd] = v;
    }
}

// ================= fc2 (tf32, CTA 128x96, 192thr) =================
__global__ __launch_bounds__(192) void fc2_kernel(
    const float* __restrict__ W2, const float* __restrict__ b2,
    const float* __restrict__ bn2, const float* __restrict__ x,
    float* __restrict__ out) {
    const int b = blockIdx.z, m0 = blockIdx.y*128, c0 = blockIdx.x*96;
    __shared__ float As[128*PAD], Bs[96*PAD];
    const int tid = threadIdx.x, lane = tid & 31, wid = tid >> 5;
    const int wm = wid & 1, wn = wid >> 1, g = lane >> 2, tig = lane & 3;
    float acc[4][4][4] = {};
    const float* Gb = g_gg + (size_t)b * Nn * HD;
    for (int k0 = 0; k0 < HD; k0 += 32) {
        load_kmajor<128,192>(As, Gb + (size_t)m0*HD + k0, HD, tid);
        load_kmajor<96,192>(Bs, W2 + (size_t)c0*HD + k0, HD, tid);
        __syncthreads();
        mma_chunk(As, Bs, acc, wm, wn, g, tig);
        __syncthreads();
    }
#pragma unroll
    for (int nt = 0; nt < 4; nt++) {
        int c = c0 + wn*32 + nt*8 + tig*2;
        float s0 = bn2[c]   * rsqrtf(bn2[576+c]   + BNEPS);
        float s1 = bn2[c+1] * rsqrtf(bn2[576+c+1] + BNEPS);
        float h0 = bn2[192+c]   + (b2[c]   - bn2[384+c])   * s0;
        float h1 = bn2[192+c+1] + (b2[c+1] - bn2[384+c+1]) * s1;
#pragma unroll
        for (int mt = 0; mt < 4; mt++) {
            int m = m0 + wm*64 + mt*16 + g;
            size_t i00 = ((size_t)b*Cc + c)*Nn + m;    // out[c][m]
            out[i00]          = acc[mt][nt][0]*s0 + h0 + x[i00];
            out[i00 + Nn]     = acc[mt][nt][1]*s1 + h1 + x[i00 + Nn];
            out[i00 + 8]      = acc[mt][nt][2]*s0 + h0 + x[i00 + 8];
            out[i00 + Nn + 8] = acc[mt][nt][3]*s1 + h1 + x[i00 + Nn + 8];
        }
    }
}

// ================= launch (single stream, 6 kernels) =================
extern "C" void kernel_launch(void* const* d_in, const int* in_sizes, int n_in,
                              void* d_out, int out_size) {
    const float* x       = (const float*)d_in[0];
    const float* W1      = (const float*)d_in[1];
    const float* b1      = (const float*)d_in[2];
    const float* bn1     = (const float*)d_in[3];
    const float* Wg      = (const float*)d_in[4];
    const float* att_src = (const float*)d_in[5];
    const float* att_dst = (const float*)d_in[6];
    const float* bg      = (const float*)d_in[7];
    const float* bng     = (const float*)d_in[8];
    const float* W2      = (const float*)d_in[9];
    const float* b2      = (const float*)d_in[10];
    const float* bn2     = (const float*)d_in[11];
    float* out = (float*)d_out;

    const int dist_smem = 2 * 4 * DBUF * (int)sizeof(float);   // 81920 B
    cudaFuncSetAttribute(dist_kernel,
                         cudaFuncAttributeMaxDynamicSharedMemorySize, dist_smem);

    pre_kernel<<<288, 256>>>(x, W1, b1, bn1, Wg, att_src, att_dst);  // 1: wsd+fc1
    node_stats_kernel<<<512, 256>>>();                               // 2
    dist_kernel<<<dim3(36, 1, Bq), 512, dist_smem>>>();              // 3
    mid_kernel<<<896, 256>>>(Wg);                                    // 4: topk+hgemm
    gat_kernel<<<Bq*Nn, 192>>>(bg, bng);                             // 5
    fc2_kernel<<<dim3(2, 8, Bq), 192>>>(W2, b2, bn2, x, out);        // 6
}